// round 9
// baseline (speedup 1.0000x reference)
#include <cuda_runtime.h>
#include <cstdint>

// Problem constants
#define T_    2048
#define HID_  2048
#define H_    16
#define HKV_  8
#define D_    128
#define I_    8192
static constexpr float EPS_   = 1e-6f;
static constexpr float SCALE_ = 0.08838834764831845f; // 1/sqrt(128)

// ---------------- scratch (static device globals; no runtime alloc) -------
__device__ float g_x  [(size_t)T_ * HID_];
__device__ float g_h  [(size_t)T_ * HID_];
__device__ float g_q  [(size_t)T_ * H_   * D_];
__device__ float g_k  [(size_t)T_ * HKV_ * D_];
__device__ float g_v  [(size_t)T_ * HKV_ * D_];
__device__ float g_vT [(size_t)HKV_ * D_ * T_];
__device__ float g_sc [(size_t)H_ * T_ * T_];       // scores / attn (in-place)
__device__ float g_ao [(size_t)T_ * H_ * D_];
__device__ float g_hid[(size_t)T_ * HID_];
__device__ float g_h2 [(size_t)T_ * HID_];
__device__ float g_gu [(size_t)T_ * 2 * I_];
__device__ float g_act[(size_t)T_ * I_];
__device__ float g_hf [(size_t)T_ * HID_];

// ---------------- helpers --------------------------------------------------
__device__ __forceinline__ uint32_t f2tf(uint32_t x) {
    uint32_t u;
    asm("cvt.rna.tf32.f32 %0, %1;" : "=r"(u) : "r"(x));
    return u;
}
__device__ __forceinline__ float tfr(float x) {   // round fp32 -> tf32-precision fp32
    uint32_t u;
    asm("cvt.rna.tf32.f32 %0, %1;" : "=r"(u) : "r"(__float_as_uint(x)));
    return __uint_as_float(u);
}

__device__ __forceinline__ void mma_tf32(float* d, const uint32_t* a, const uint32_t* b) {
    asm volatile(
        "mma.sync.aligned.m16n8k8.row.col.f32.tf32.tf32.f32 "
        "{%0,%1,%2,%3},{%4,%5,%6,%7},{%8,%9},{%0,%1,%2,%3};\n"
        : "+f"(d[0]), "+f"(d[1]), "+f"(d[2]), "+f"(d[3])
        : "r"(a[0]), "r"(a[1]), "r"(a[2]), "r"(a[3]), "r"(b[0]), "r"(b[1]));
}

__device__ __forceinline__ void cp16(uint32_t dst, const float* src) {
    asm volatile("cp.async.cg.shared.global [%0], [%1], 16;\n" :: "r"(dst), "l"(src));
}
__device__ __forceinline__ void cp_commit() { asm volatile("cp.async.commit_group;\n"); }
template <int N>
__device__ __forceinline__ void cp_wait() { asm volatile("cp.async.wait_group %0;\n" :: "n"(N)); }

// ---------------- generic TF32 GEMM: C = alpha * A(MxK) * B(NxK)^T (+ R) ---
// Tile 128(M) x 64(N) x 32(K), 8 warps of 32x32, 2-stage cp.async, 3 CTAs/SM.
// A (activations, L2-resident) is the operand replicated across bn tiles;
// B (weights) traffic stays 1x.
// If C2 != nullptr: z==1 switches to (B2, C2) (merged dual-GEMM launch).
// Else batched: Abase=A+z*sA, Bbase=B+(z/bDiv)*sB, Cbase=C+z*sC.
// causal: 0 none, 1 skip tiles with bn*64 > bm*128+127 (scores),
//         2 cap K at (bm+1)*BM (PV).
static constexpr int BM_ = 128, BN_ = 64, BK_ = 32, BKP_ = 36, STG_ = 2;
static constexpr int AW_ = BM_ * BKP_;   // A stage words  (4608)
static constexpr int BW_ = BN_ * BKP_;   // B stage words  (2304)
static constexpr int GEMM_SMEM_ = (STG_ * AW_ + STG_ * BW_) * 4;  // 55296 B

template <int EPI, int CVTB, int RC>
__global__ void __launch_bounds__(256, 3) gemm_tt(
    const float* __restrict__ A, long lda, long sA,
    const float* __restrict__ B, long ldb, long sB, int bDiv,
    float* __restrict__ C, long ldc, long sC,
    const float* __restrict__ R, long ldr,
    const float* __restrict__ B2, float* __restrict__ C2,
    int K, float alpha, int causal)
{
    extern __shared__ float sm[];

    int bm = blockIdx.y, bn = blockIdx.x, z = blockIdx.z;
    if (causal == 1 && bn * BN_ > bm * BM_ + BM_ - 1) return;

    if (C2 != nullptr) {
        if (z == 1) { B = B2; C = C2; }
    } else {
        A += (size_t)z * sA;
        B += (size_t)(z / bDiv) * sB;
        C += (size_t)z * sC;
    }

    int tid = threadIdx.x, lane = tid & 31, warp = tid >> 5;
    int wm = (warp & 3) * 32, wn = (warp >> 2) * 32;
    int lr = tid >> 3, lc = (tid & 7) * 4;     // lr 0..31, lc 0..28

    const float* Ag = A + (size_t)(bm * BM_ + lr) * lda + lc;
    const float* Bg = B + (size_t)(bn * BN_ + lr) * ldb + lc;

    uint32_t smemB = (uint32_t)__cvta_generic_to_shared(sm);
    uint32_t aDst  = smemB + (uint32_t)(lr * BKP_ + lc) * 4;
    uint32_t bDst  = smemB + (uint32_t)(STG_ * AW_ + lr * BKP_ + lc) * 4;

    int KT = K / BK_;
    if (causal == 2) {
        int cap = (bm + 1) * (BM_ / BK_);
        if (cap < KT) KT = cap;
    }

    auto issue = [&](int stage, int kt) {
        uint32_t soA = (uint32_t)(stage * AW_) * 4;
        uint32_t soB = (uint32_t)(stage * BW_) * 4;
        const float* Ap = Ag + (size_t)kt * BK_;
        const float* Bp = Bg + (size_t)kt * BK_;
#pragma unroll
        for (int i = 0; i < 4; i++)
            cp16(aDst + soA + (uint32_t)(32 * i * BKP_) * 4, Ap + (size_t)(32 * i) * lda);
#pragma unroll
        for (int i = 0; i < 2; i++)
            cp16(bDst + soB + (uint32_t)(32 * i * BKP_) * 4, Bp + (size_t)(32 * i) * ldb);
    };

    float acc[2][4][4];
#pragma unroll
    for (int i = 0; i < 2; i++)
#pragma unroll
        for (int j = 0; j < 4; j++)
#pragma unroll
            for (int c = 0; c < 4; c++) acc[i][j][c] = 0.f;

    // prefetch stage 0
    issue(0, 0);
    cp_commit();

    const uint32_t* smw = (const uint32_t*)sm;
    for (int kt = 0; kt < KT; kt++) {
        cp_wait<0>();
        __syncthreads();   // readers of the slot being overwritten below are done

        int nk = kt + 1;
        if (nk < KT) issue(nk & 1, nk);
        cp_commit();

        int buf = kt & 1;
        const uint32_t* Ab = smw + buf * AW_;
        const uint32_t* Bb = smw + STG_ * AW_ + buf * BW_;
#pragma unroll
        for (int kk = 0; kk < 4; kk++) {
            int k8 = kk * 8;
            uint32_t af[2][4], bf[4][2];
#pragma unroll
            for (int mt = 0; mt < 2; mt++) {
                const uint32_t* p = Ab + (wm + mt * 16 + (lane >> 2)) * BKP_ + k8 + (lane & 3);
                af[mt][0] = p[0];
                af[mt][1] = p[8 * BKP_];
                af[mt][2] = p[4];
                af[mt][3] = p[8 * BKP_ + 4];
            }
#pragma unroll
            for (int nt = 0; nt < 4; nt++) {
                const uint32_t* p = Bb + (wn + nt * 8 + (lane >> 2)) * BKP_ + k8 + (lane & 3);
                if (CVTB) {
                    bf[nt][0] = f2tf(p[0]);
                    bf[nt][1] = f2tf(p[4]);
                } else {
                    bf[nt][0] = p[0];
                    bf[nt][1] = p[4];
                }
            }
#pragma unroll
            for (int mt = 0; mt < 2; mt++)
#pragma unroll
                for (int nt = 0; nt < 4; nt++)
                    mma_tf32(acc[mt][nt], af[mt], bf[nt]);
        }
    }

#pragma unroll
    for (int mt = 0; mt < 2; mt++) {
        size_t row = (size_t)bm * BM_ + wm + mt * 16 + (lane >> 2);
#pragma unroll
        for (int nt = 0; nt < 4; nt++) {
            size_t col = (size_t)bn * BN_ + wn + nt * 8 + 2 * (lane & 3);
            float2 v0 = make_float2(acc[mt][nt][0] * alpha, acc[mt][nt][1] * alpha);
            float2 v1 = make_float2(acc[mt][nt][2] * alpha, acc[mt][nt][3] * alpha);
            if (EPI == 1) {
                const float* r0 = R + row * ldr + col;
                const float* r1 = R + (row + 8) * ldr + col;
                v0.x += r0[0]; v0.y += r0[1];
                v1.x += r1[0]; v1.y += r1[1];
            }
            if (RC) {
                v0.x = tfr(v0.x); v0.y = tfr(v0.y);
                v1.x = tfr(v1.x); v1.y = tfr(v1.y);
            }
            *(float2*)(C + row * ldc + col) = v0;
            *(float2*)(C + (row + 8) * ldc + col) = v1;
        }
    }
}

// ---------------- transpose: src (Mrows x Ncols) -> dst (Ncols x Mrows) ----
template <int RND>
__global__ void transpose_k(const float* __restrict__ src, float* __restrict__ dst,
                            int Mrows, int Ncols)
{
    __shared__ float tile[32][33];
    int x  = blockIdx.x * 32 + threadIdx.x;
    int y0 = blockIdx.y * 32 + threadIdx.y;
#pragma unroll
    for (int i = 0; i < 32; i += 8)
        tile[threadIdx.y + i][threadIdx.x] = src[(size_t)(y0 + i) * Ncols + x];
    __syncthreads();
    int x2 = blockIdx.y * 32 + threadIdx.x;
    int y2 = blockIdx.x * 32 + threadIdx.y;
#pragma unroll
    for (int i = 0; i < 32; i += 8) {
        float v = tile[threadIdx.x][threadIdx.y + i];
        if (RND) v = tfr(v);
        dst[(size_t)(y2 + i) * Mrows + x2] = v;
    }
}

// ---------------- RMSNorm over rows of length HID_ (tf32-rounded output) ---
__global__ void rmsnorm_k(const float* __restrict__ X, const float* __restrict__ w,
                          float* __restrict__ O)
{
    int row = blockIdx.x, tid = threadIdx.x;
    const float4* x  = (const float4*)(X + (size_t)row * HID_);
    float4*       o  = (float4*)(O + (size_t)row * HID_);
    const float4* wv = (const float4*)w;

    float ss = 0.f;
    float4 v[2];
#pragma unroll
    for (int i = 0; i < 2; i++) {
        v[i] = x[tid + i * 256];
        ss += v[i].x * v[i].x + v[i].y * v[i].y + v[i].z * v[i].z + v[i].w * v[i].w;
    }
    __shared__ float red[8];
#pragma unroll
    for (int off = 16; off; off >>= 1) ss += __shfl_xor_sync(0xffffffffu, ss, off);
    if ((tid & 31) == 0) red[tid >> 5] = ss;
    __syncthreads();
    float tot = 0.f;
#pragma unroll
    for (int i = 0; i < 8; i++) tot += red[i];
    float rms = rsqrtf(tot / HID_ + EPS_);
#pragma unroll
    for (int i = 0; i < 2; i++) {
        float4 ww = wv[tid + i * 256];
        o[tid + i * 256] = make_float4(tfr(v[i].x * rms * ww.x), tfr(v[i].y * rms * ww.y),
                                       tfr(v[i].z * rms * ww.z), tfr(v[i].w * rms * ww.w));
    }
}

// ------- fused per-head RMSNorm + RoPE, tf32-rounded output ----------------
__global__ void qknorm_rope_k(float* __restrict__ Q, int NH, const float* __restrict__ w,
                              const float* __restrict__ cs, const float* __restrict__ sn)
{
    int r    = blockIdx.x * 8 + (threadIdx.x >> 5);
    int lane = threadIdx.x & 31;
    int t    = r / NH;
    float* p = Q + (size_t)r * 128;

    float4 v = ((float4*)p)[lane];
    float ss = v.x * v.x + v.y * v.y + v.z * v.z + v.w * v.w;
#pragma unroll
    for (int off = 16; off; off >>= 1) ss += __shfl_xor_sync(0xffffffffu, ss, off);
    float rms = rsqrtf(ss / 128.f + EPS_);

    float4 ww = ((const float4*)w)[lane];
    float4 nv = make_float4(v.x * rms * ww.x, v.y * rms * ww.y,
                            v.z * rms * ww.z, v.w * rms * ww.w);
    float4 pv;
    pv.x = __shfl_xor_sync(0xffffffffu, nv.x, 16);
    pv.y = __shfl_xor_sync(0xffffffffu, nv.y, 16);
    pv.z = __shfl_xor_sync(0xffffffffu, nv.z, 16);
    pv.w = __shfl_xor_sync(0xffffffffu, nv.w, 16);
    float sgn = (lane < 16) ? -1.f : 1.f;

    float4 cv = ((const float4*)(cs + (size_t)t * 128))[lane];
    float4 sv = ((const float4*)(sn + (size_t)t * 128))[lane];
    float4 out;
    out.x = tfr(nv.x * cv.x + sgn * pv.x * sv.x);
    out.y = tfr(nv.y * cv.y + sgn * pv.y * sv.y);
    out.z = tfr(nv.z * cv.z + sgn * pv.z * sv.z);
    out.w = tfr(nv.w * cv.w + sgn * pv.w * sv.w);
    ((float4*)p)[lane] = out;
}

// -------- causal softmax, in-place; zeros masked tail; rounded output ------
__global__ void softmax_causal_k(float* __restrict__ sc)
{
    int t = blockIdx.x, h = blockIdx.y, tid = threadIdx.x;
    float* row = sc + ((size_t)h * T_ + t) * T_;
    int n = t + 1;

    __shared__ float red[8];
    float mx = -1e30f;
    for (int j = tid; j < n; j += 256) mx = fmaxf(mx, row[j]);
#pragma unroll
    for (int off = 16; off; off >>= 1) mx = fmaxf(mx, __shfl_xor_sync(0xffffffffu, mx, off));
    if ((tid & 31) == 0) red[tid >> 5] = mx;
    __syncthreads();
    float m = fmaxf(fmaxf(fmaxf(red[0], red[1]), fmaxf(red[2], red[3])),
                    fmaxf(fmaxf(red[4], red[5]), fmaxf(red[6], red[7])));
    __syncthreads();

    float s = 0.f;
    for (int j = tid; j < n; j += 256) {
        float e = __expf(row[j] - m);
        row[j] = e;
        s += e;
    }
#pragma unroll
    for (int off = 16; off; off >>= 1) s += __shfl_xor_sync(0xffffffffu, s, off);
    if ((tid & 31) == 0) red[tid >> 5] = s;
    __syncthreads();
    float tot = red[0] + red[1] + red[2] + red[3] + red[4] + red[5] + red[6] + red[7];
    float inv = 1.f / tot;

    for (int j = tid; j < T_; j += 256) row[j] = (j < n) ? tfr(row[j] * inv) : 0.f;
}

// ---------------- SwiGLU: act = silu(gate) * up  (rounded output) ----------
__global__ void swiglu_k(const float* __restrict__ gu, float* __restrict__ act)
{
    size_t i = (size_t)blockIdx.x * 256 + threadIdx.x;
    size_t t = i / (I_ / 4);
    size_t j = i % (I_ / 4);
    float4 g4 = ((const float4*)(gu + t * 2 * I_))[j];
    float4 u4 = ((const float4*)(gu + t * 2 * I_ + I_))[j];
    float4 o;
    o.x = tfr(g4.x / (1.f + __expf(-g4.x)) * u4.x);
    o.y = tfr(g4.y / (1.f + __expf(-g4.y)) * u4.y);
    o.z = tfr(g4.z / (1.f + __expf(-g4.z)) * u4.z);
    o.w = tfr(g4.w / (1.f + __expf(-g4.w)) * u4.w);
    ((float4*)(act + t * I_))[j] = o;
}

// ---------------- host orchestration ---------------------------------------
extern "C" void kernel_launch(void* const* d_in, const int* in_sizes, int n_in,
                              void* d_out, int out_size)
{
    (void)in_sizes; (void)n_in; (void)out_size;
    const float* hc  = (const float*)d_in[0];
    const float* cs  = (const float*)d_in[1];
    const float* sn  = (const float*)d_in[2];
    // d_in[3] causal_mask, d_in[4] kv_cache: dead (cache region fully masked)
    const float* wq  = (const float*)d_in[5];
    const float* wk  = (const float*)d_in[6];
    const float* wv  = (const float*)d_in[7];
    const float* wo  = (const float*)d_in[8];
    const float* wgu = (const float*)d_in[9];
    const float* wdn = (const float*)d_in[10];
    const float* iln = (const float*)d_in[11];
    const float* pln = (const float*)d_in[12];
    const float* qnw = (const float*)d_in[13];
    const float* knw = (const float*)d_in[14];
    float* out = (float*)d_out;

    float *x, *h, *q, *k, *v, *vT, *sc, *ao, *hid, *h2, *gu, *act, *hf;
    cudaGetSymbolAddress((void**)&x,   g_x);
    cudaGetSymbolAddress((void**)&h,   g_h);
    cudaGetSymbolAddress((void**)&q,   g_q);
    cudaGetSymbolAddress((void**)&k,   g_k);
    cudaGetSymbolAddress((void**)&v,   g_v);
    cudaGetSymbolAddress((void**)&vT,  g_vT);
    cudaGetSymbolAddress((void**)&sc,  g_sc);
    cudaGetSymbolAddress((void**)&ao,  g_ao);
    cudaGetSymbolAddress((void**)&hid, g_hid);
    cudaGetSymbolAddress((void**)&h2,  g_h2);
    cudaGetSymbolAddress((void**)&gu,  g_gu);
    cudaGetSymbolAddress((void**)&act, g_act);
    cudaGetSymbolAddress((void**)&hf,  g_hf);

    cudaFuncSetAttribute((const void*)gemm_tt<0,1,0>, cudaFuncAttributeMaxDynamicSharedMemorySize, GEMM_SMEM_);
    cudaFuncSetAttribute((const void*)gemm_tt<0,0,0>, cudaFuncAttributeMaxDynamicSharedMemorySize, GEMM_SMEM_);
    cudaFuncSetAttribute((const void*)gemm_tt<0,0,1>, cudaFuncAttributeMaxDynamicSharedMemorySize, GEMM_SMEM_);
    cudaFuncSetAttribute((const void*)gemm_tt<1,1,0>, cudaFuncAttributeMaxDynamicSharedMemorySize, GEMM_SMEM_);

    dim3 tb(32, 8);

    // x = hidden_conv^T  (HID x T -> T x HID)
    transpose_k<0><<<dim3(T_ / 32, HID_ / 32), tb>>>(hc, x, HID_, T_);
    // h = rmsnorm(x) * input_ln_w  (tf32-rounded)
    rmsnorm_k<<<T_, 256>>>(x, iln, h);
    // Q projection
    gemm_tt<0,1,0><<<dim3(32, 16, 1), 256, GEMM_SMEM_>>>(h, HID_, 0, wq, HID_, 0, 1,
        q, H_ * D_, 0, nullptr, 0, nullptr, nullptr, HID_, 1.f, 0);
    // K and V projections merged into one launch (z picks B/C)
    gemm_tt<0,1,0><<<dim3(16, 16, 2), 256, GEMM_SMEM_>>>(h, HID_, 0, wk, HID_, 0, 1,
        k, HKV_ * D_, 0, nullptr, 0, wv, v, HID_, 1.f, 0);
    // per-head rmsnorm + rope (rounded)
    qknorm_rope_k<<<T_ * H_ / 8, 256>>>(q, H_, qnw, cs, sn);
    qknorm_rope_k<<<T_ * HKV_ / 8, 256>>>(k, HKV_, knw, cs, sn);
    // vT for PV gemm (rounded during transpose)
    transpose_k<1><<<dim3((HKV_ * D_) / 32, T_ / 32), tb>>>(v, vT, T_, HKV_ * D_);
    // scores = SCALE * q k^T per head (causal tiles only; operands pre-rounded)
    gemm_tt<0,0,0><<<dim3(32, 16, H_), 256, GEMM_SMEM_>>>(q, H_ * D_, D_,
        k, HKV_ * D_, D_, 2, sc, T_, (long)T_ * T_, nullptr, 0, nullptr, nullptr, D_, SCALE_, 1);
    // causal softmax in-place (rounded; zeros masked tail)
    softmax_causal_k<<<dim3(T_, H_), 256>>>(sc);
    // attn @ V  (K capped causally; output rounded for O-proj consumption)
    gemm_tt<0,0,1><<<dim3(2, 16, H_), 256, GEMM_SMEM_>>>(sc, T_, (long)T_ * T_,
        vT, T_, (long)D_ * T_, 2, ao, H_ * D_, D_, nullptr, 0, nullptr, nullptr, T_, 1.f, 2);
    // hidden = x + ao @ wo^T
    gemm_tt<1,1,0><<<dim3(32, 16, 1), 256, GEMM_SMEM_>>>(ao, H_ * D_, 0, wo, H_ * D_, 0, 1,
        hid, HID_, 0, x, HID_, nullptr, nullptr, H_ * D_, 1.f, 0);
    // h2 = rmsnorm(hidden) * post_ln_w  (rounded)
    rmsnorm_k<<<T_, 256>>>(hid, pln, h2);
    // gu = h2 @ w_gate_up^T
    gemm_tt<0,1,0><<<dim3(256, 16, 1), 256, GEMM_SMEM_>>>(h2, HID_, 0, wgu, HID_, 0, 1,
        gu, 2 * I_, 0, nullptr, 0, nullptr, nullptr, HID_, 1.f, 0);
    // act = silu(gate) * up  (rounded)
    swiglu_k<<<(T_ * I_ / 4) / 256, 256>>>(gu, act);
    // hf = hidden + act @ w_down^T
    gemm_tt<1,1,0><<<dim3(32, 16, 1), 256, GEMM_SMEM_>>>(act, I_, 0, wdn, I_, 0, 1,
        hf, HID_, 0, hid, HID_, nullptr, nullptr, I_, 1.f, 0);
    // out = hf^T  (T x HID -> HID x T)
    transpose_k<0><<<dim3(HID_ / 32, T_ / 32), tb>>>(hf, out, T_, HID_);
}

// round 13
// speedup vs baseline: 1.2354x; 1.2354x over previous
#include <cuda_runtime.h>
#include <cstdint>

// Problem constants
#define T_    2048
#define HID_  2048
#define H_    16
#define HKV_  8
#define D_    128
#define I_    8192
static constexpr float EPS_   = 1e-6f;
static constexpr float SCALE_ = 0.08838834764831845f; // 1/sqrt(128)

// ---------------- scratch (static device globals; no runtime alloc) -------
__device__ float g_x  [(size_t)T_ * HID_];
__device__ float g_h  [(size_t)T_ * HID_];
__device__ float g_q  [(size_t)T_ * H_   * D_];
__device__ float g_k  [(size_t)T_ * HKV_ * D_];
__device__ float g_v  [(size_t)T_ * HKV_ * D_];
__device__ float g_vT [(size_t)HKV_ * D_ * T_];
__device__ float g_sc [(size_t)H_ * T_ * T_];       // scores / attn (in-place)
__device__ float g_ao [(size_t)T_ * H_ * D_];
__device__ float g_hid[(size_t)T_ * HID_];
__device__ float g_h2 [(size_t)T_ * HID_];
__device__ float g_gu [(size_t)T_ * 2 * I_];
__device__ float g_act[(size_t)T_ * I_];
__device__ float g_hf [(size_t)T_ * HID_];

// ---------------- helpers --------------------------------------------------
__device__ __forceinline__ uint32_t f2tf(uint32_t x) {
    uint32_t u;
    asm("cvt.rna.tf32.f32 %0, %1;" : "=r"(u) : "r"(x));
    return u;
}
__device__ __forceinline__ float tfr(float x) {   // round fp32 -> tf32-precision fp32
    uint32_t u;
    asm("cvt.rna.tf32.f32 %0, %1;" : "=r"(u) : "r"(__float_as_uint(x)));
    return __uint_as_float(u);
}

__device__ __forceinline__ void mma_tf32(float* d, const uint32_t* a, const uint32_t* b) {
    asm volatile(
        "mma.sync.aligned.m16n8k8.row.col.f32.tf32.tf32.f32 "
        "{%0,%1,%2,%3},{%4,%5,%6,%7},{%8,%9},{%0,%1,%2,%3};\n"
        : "+f"(d[0]), "+f"(d[1]), "+f"(d[2]), "+f"(d[3])
        : "r"(a[0]), "r"(a[1]), "r"(a[2]), "r"(a[3]), "r"(b[0]), "r"(b[1]));
}

__device__ __forceinline__ void cp16(uint32_t dst, const float* src) {
    asm volatile("cp.async.cg.shared.global [%0], [%1], 16;\n" :: "r"(dst), "l"(src));
}
__device__ __forceinline__ void cp_commit() { asm volatile("cp.async.commit_group;\n"); }
template <int N>
__device__ __forceinline__ void cp_wait() { asm volatile("cp.async.wait_group %0;\n" :: "n"(N)); }

// ---------------- generic TF32 GEMM: C = alpha * A(MxK) * B(NxK)^T (+ R) ---
// Tile 128x128x32. 4 warps of 64x64 (128 threads) -> LDS bytes/MMA halved vs
// 8x(64x32): crossbar demand ~= tensor demand. 3-stage cp.async, one barrier
// per K-tile, 2 CTAs/SM.
// If C2 != nullptr: z==1 switches to (B2, C2) (merged dual-GEMM launch).
// Else batched: Abase=A+z*sA, Bbase=B+(z/bDiv)*sB, Cbase=C+z*sC.
// causal: 0 none, 1 skip tiles bn>bm (scores), 2 cap K at (bm+1)*BM (PV).
static constexpr int BM_ = 128, BN_ = 128, BK_ = 32, BKP_ = 36, STG_ = 3;
static constexpr int TW_ = BM_ * BKP_;
static constexpr int GEMM_SMEM_ = STG_ * 2 * TW_ * 4;   // 110592 B -> 2 CTAs/SM

template <int EPI, int CVTB, int RC>
__global__ void __launch_bounds__(128, 2) gemm_tt(
    const float* __restrict__ A, long lda, long sA,
    const float* __restrict__ B, long ldb, long sB, int bDiv,
    float* __restrict__ C, long ldc, long sC,
    const float* __restrict__ R, long ldr,
    const float* __restrict__ B2, float* __restrict__ C2,
    int K, float alpha, int causal)
{
    extern __shared__ float sm[];

    int bm = blockIdx.y, bn = blockIdx.x, z = blockIdx.z;
    if (causal == 1 && bn > bm) return;

    if (C2 != nullptr) {
        if (z == 1) { B = B2; C = C2; }
    } else {
        A += (size_t)z * sA;
        B += (size_t)(z / bDiv) * sB;
        C += (size_t)z * sC;
    }

    int tid = threadIdx.x, lane = tid & 31, warp = tid >> 5;
    int wm = (warp & 1) * 64, wn = (warp >> 1) * 64;
    int lr = tid >> 3, lc = (tid & 7) * 4;   // lr 0..15, lc 0,4,...,28

    const float* Ag = A + (size_t)(bm * BM_ + lr) * lda + lc;
    const float* Bg = B + (size_t)(bn * BN_ + lr) * ldb + lc;

    uint32_t smemB = (uint32_t)__cvta_generic_to_shared(sm);
    uint32_t aDst  = smemB + (uint32_t)(lr * BKP_ + lc) * 4;
    uint32_t bDst  = smemB + (uint32_t)(STG_ * TW_ + lr * BKP_ + lc) * 4;

    int KT = K / BK_;
    if (causal == 2) {
        int cap = (bm + 1) * (BM_ / BK_);
        if (cap < KT) KT = cap;
    }

    auto issue = [&](int stage, int kt) {
        uint32_t so = (uint32_t)(stage * TW_) * 4;
        const float* Ap = Ag + (size_t)kt * BK_;
        const float* Bp = Bg + (size_t)kt * BK_;
#pragma unroll
        for (int i = 0; i < 8; i++) {
            cp16(aDst + so + (uint32_t)(16 * i * BKP_) * 4, Ap + (size_t)(16 * i) * lda);
            cp16(bDst + so + (uint32_t)(16 * i * BKP_) * 4, Bp + (size_t)(16 * i) * ldb);
        }
    };

    float acc[4][8][4];
#pragma unroll
    for (int i = 0; i < 4; i++)
#pragma unroll
        for (int j = 0; j < 8; j++)
#pragma unroll
            for (int c = 0; c < 4; c++) acc[i][j][c] = 0.f;

#pragma unroll
    for (int s = 0; s < STG_ - 1; s++) {
        if (s < KT) issue(s, s);
        cp_commit();
    }

    const uint32_t* smw = (const uint32_t*)sm;
    for (int kt = 0; kt < KT; kt++) {
        cp_wait<STG_ - 2>();
        __syncthreads();   // readers of the slot overwritten below finished last iter

        int nk = kt + STG_ - 1;
        if (nk < KT) issue(nk % STG_, nk);
        cp_commit();

        int buf = kt % STG_;
        const uint32_t* Ab = smw + buf * TW_;
        const uint32_t* Bb = smw + (STG_ + buf) * TW_;
#pragma unroll
        for (int kk = 0; kk < 4; kk++) {
            int k8 = kk * 8;
            uint32_t af[4][4], bf[8][2];
#pragma unroll
            for (int mt = 0; mt < 4; mt++) {
                const uint32_t* p = Ab + (wm + mt * 16 + (lane >> 2)) * BKP_ + k8 + (lane & 3);
                af[mt][0] = p[0];
                af[mt][1] = p[8 * BKP_];
                af[mt][2] = p[4];
                af[mt][3] = p[8 * BKP_ + 4];
            }
#pragma unroll
            for (int nt = 0; nt < 8; nt++) {
                const uint32_t* p = Bb + (wn + nt * 8 + (lane >> 2)) * BKP_ + k8 + (lane & 3);
                if (CVTB) {
                    bf[nt][0] = f2tf(p[0]);
                    bf[nt][1] = f2tf(p[4]);
                } else {
                    bf[nt][0] = p[0];
                    bf[nt][1] = p[4];
                }
            }
#pragma unroll
            for (int mt = 0; mt < 4; mt++)
#pragma unroll
                for (int nt = 0; nt < 8; nt++)
                    mma_tf32(acc[mt][nt], af[mt], bf[nt]);
        }
    }

#pragma unroll
    for (int mt = 0; mt < 4; mt++) {
        size_t row = (size_t)bm * BM_ + wm + mt * 16 + (lane >> 2);
#pragma unroll
        for (int nt = 0; nt < 8; nt++) {
            size_t col = (size_t)bn * BN_ + wn + nt * 8 + 2 * (lane & 3);
            float2 v0 = make_float2(acc[mt][nt][0] * alpha, acc[mt][nt][1] * alpha);
            float2 v1 = make_float2(acc[mt][nt][2] * alpha, acc[mt][nt][3] * alpha);
            if (EPI == 1) {
                const float* r0 = R + row * ldr + col;
                const float* r1 = R + (row + 8) * ldr + col;
                v0.x += r0[0]; v0.y += r0[1];
                v1.x += r1[0]; v1.y += r1[1];
            }
            if (RC) {
                v0.x = tfr(v0.x); v0.y = tfr(v0.y);
                v1.x = tfr(v1.x); v1.y = tfr(v1.y);
            }
            *(float2*)(C + row * ldc + col) = v0;
            *(float2*)(C + (row + 8) * ldc + col) = v1;
        }
    }
}

// ---------------- transpose: src (Mrows x Ncols) -> dst (Ncols x Mrows) ----
template <int RND>
__global__ void transpose_k(const float* __restrict__ src, float* __restrict__ dst,
                            int Mrows, int Ncols)
{
    __shared__ float tile[32][33];
    int x  = blockIdx.x * 32 + threadIdx.x;
    int y0 = blockIdx.y * 32 + threadIdx.y;
#pragma unroll
    for (int i = 0; i < 32; i += 8)
        tile[threadIdx.y + i][threadIdx.x] = src[(size_t)(y0 + i) * Ncols + x];
    __syncthreads();
    int x2 = blockIdx.y * 32 + threadIdx.x;
    int y2 = blockIdx.x * 32 + threadIdx.y;
#pragma unroll
    for (int i = 0; i < 32; i += 8) {
        float v = tile[threadIdx.x][threadIdx.y + i];
        if (RND) v = tfr(v);
        dst[(size_t)(y2 + i) * Mrows + x2] = v;
    }
}

// ---------------- RMSNorm over rows of length HID_ (tf32-rounded output) ---
__global__ void rmsnorm_k(const float* __restrict__ X, const float* __restrict__ w,
                          float* __restrict__ O)
{
    int row = blockIdx.x, tid = threadIdx.x;
    const float4* x  = (const float4*)(X + (size_t)row * HID_);
    float4*       o  = (float4*)(O + (size_t)row * HID_);
    const float4* wv = (const float4*)w;

    float ss = 0.f;
    float4 v[2];
#pragma unroll
    for (int i = 0; i < 2; i++) {
        v[i] = x[tid + i * 256];
        ss += v[i].x * v[i].x + v[i].y * v[i].y + v[i].z * v[i].z + v[i].w * v[i].w;
    }
    __shared__ float red[8];
#pragma unroll
    for (int off = 16; off; off >>= 1) ss += __shfl_xor_sync(0xffffffffu, ss, off);
    if ((tid & 31) == 0) red[tid >> 5] = ss;
    __syncthreads();
    float tot = 0.f;
#pragma unroll
    for (int i = 0; i < 8; i++) tot += red[i];
    float rms = rsqrtf(tot / HID_ + EPS_);
#pragma unroll
    for (int i = 0; i < 2; i++) {
        float4 ww = wv[tid + i * 256];
        o[tid + i * 256] = make_float4(tfr(v[i].x * rms * ww.x), tfr(v[i].y * rms * ww.y),
                                       tfr(v[i].z * rms * ww.z), tfr(v[i].w * rms * ww.w));
    }
}

// ------- fused per-head RMSNorm + RoPE, tf32-rounded output ----------------
__global__ void qknorm_rope_k(float* __restrict__ Q, int NH, const float* __restrict__ w,
                              const float* __restrict__ cs, const float* __restrict__ sn)
{
    int r    = blockIdx.x * 8 + (threadIdx.x >> 5);
    int lane = threadIdx.x & 31;
    int t    = r / NH;
    float* p = Q + (size_t)r * 128;

    float4 v = ((float4*)p)[lane];
    float ss = v.x * v.x + v.y * v.y + v.z * v.z + v.w * v.w;
#pragma unroll
    for (int off = 16; off; off >>= 1) ss += __shfl_xor_sync(0xffffffffu, ss, off);
    float rms = rsqrtf(ss / 128.f + EPS_);

    float4 ww = ((const float4*)w)[lane];
    float4 nv = make_float4(v.x * rms * ww.x, v.y * rms * ww.y,
                            v.z * rms * ww.z, v.w * rms * ww.w);
    float4 pv;
    pv.x = __shfl_xor_sync(0xffffffffu, nv.x, 16);
    pv.y = __shfl_xor_sync(0xffffffffu, nv.y, 16);
    pv.z = __shfl_xor_sync(0xffffffffu, nv.z, 16);
    pv.w = __shfl_xor_sync(0xffffffffu, nv.w, 16);
    float sgn = (lane < 16) ? -1.f : 1.f;

    float4 cv = ((const float4*)(cs + (size_t)t * 128))[lane];
    float4 sv = ((const float4*)(sn + (size_t)t * 128))[lane];
    float4 out;
    out.x = tfr(nv.x * cv.x + sgn * pv.x * sv.x);
    out.y = tfr(nv.y * cv.y + sgn * pv.y * sv.y);
    out.z = tfr(nv.z * cv.z + sgn * pv.z * sv.z);
    out.w = tfr(nv.w * cv.w + sgn * pv.w * sv.w);
    ((float4*)p)[lane] = out;
}

// -------- causal softmax, in-place; zeros masked tail; rounded output ------
__global__ void softmax_causal_k(float* __restrict__ sc)
{
    int t = blockIdx.x, h = blockIdx.y, tid = threadIdx.x;
    float* row = sc + ((size_t)h * T_ + t) * T_;
    int n = t + 1;

    __shared__ float red[8];
    float mx = -1e30f;
    for (int j = tid; j < n; j += 256) mx = fmaxf(mx, row[j]);
#pragma unroll
    for (int off = 16; off; off >>= 1) mx = fmaxf(mx, __shfl_xor_sync(0xffffffffu, mx, off));
    if ((tid & 31) == 0) red[tid >> 5] = mx;
    __syncthreads();
    float m = fmaxf(fmaxf(fmaxf(red[0], red[1]), fmaxf(red[2], red[3])),
                    fmaxf(fmaxf(red[4], red[5]), fmaxf(red[6], red[7])));
    __syncthreads();

    float s = 0.f;
    for (int j = tid; j < n; j += 256) {
        float e = __expf(row[j] - m);
        row[j] = e;
        s += e;
    }
#pragma unroll
    for (int off = 16; off; off >>= 1) s += __shfl_xor_sync(0xffffffffu, s, off);
    if ((tid & 31) == 0) red[tid >> 5] = s;
    __syncthreads();
    float tot = red[0] + red[1] + red[2] + red[3] + red[4] + red[5] + red[6] + red[7];
    float inv = 1.f / tot;

    for (int j = tid; j < T_; j += 256) row[j] = (j < n) ? tfr(row[j] * inv) : 0.f;
}

// ---------------- SwiGLU: act = silu(gate) * up  (rounded output) ----------
__global__ void swiglu_k(const float* __restrict__ gu, float* __restrict__ act)
{
    size_t i = (size_t)blockIdx.x * 256 + threadIdx.x;
    size_t t = i / (I_ / 4);
    size_t j = i % (I_ / 4);
    float4 g4 = ((const float4*)(gu + t * 2 * I_))[j];
    float4 u4 = ((const float4*)(gu + t * 2 * I_ + I_))[j];
    float4 o;
    o.x = tfr(g4.x / (1.f + __expf(-g4.x)) * u4.x);
    o.y = tfr(g4.y / (1.f + __expf(-g4.y)) * u4.y);
    o.z = tfr(g4.z / (1.f + __expf(-g4.z)) * u4.z);
    o.w = tfr(g4.w / (1.f + __expf(-g4.w)) * u4.w);
    ((float4*)(act + t * I_))[j] = o;
}

// ---------------- host orchestration ---------------------------------------
extern "C" void kernel_launch(void* const* d_in, const int* in_sizes, int n_in,
                              void* d_out, int out_size)
{
    (void)in_sizes; (void)n_in; (void)out_size;
    const float* hc  = (const float*)d_in[0];
    const float* cs  = (const float*)d_in[1];
    const float* sn  = (const float*)d_in[2];
    // d_in[3] causal_mask, d_in[4] kv_cache: dead (cache region fully masked)
    const float* wq  = (const float*)d_in[5];
    const float* wk  = (const float*)d_in[6];
    const float* wv  = (const float*)d_in[7];
    const float* wo  = (const float*)d_in[8];
    const float* wgu = (const float*)d_in[9];
    const float* wdn = (const float*)d_in[10];
    const float* iln = (const float*)d_in[11];
    const float* pln = (const float*)d_in[12];
    const float* qnw = (const float*)d_in[13];
    const float* knw = (const float*)d_in[14];
    float* out = (float*)d_out;

    float *x, *h, *q, *k, *v, *vT, *sc, *ao, *hid, *h2, *gu, *act, *hf;
    cudaGetSymbolAddress((void**)&x,   g_x);
    cudaGetSymbolAddress((void**)&h,   g_h);
    cudaGetSymbolAddress((void**)&q,   g_q);
    cudaGetSymbolAddress((void**)&k,   g_k);
    cudaGetSymbolAddress((void**)&v,   g_v);
    cudaGetSymbolAddress((void**)&vT,  g_vT);
    cudaGetSymbolAddress((void**)&sc,  g_sc);
    cudaGetSymbolAddress((void**)&ao,  g_ao);
    cudaGetSymbolAddress((void**)&hid, g_hid);
    cudaGetSymbolAddress((void**)&h2,  g_h2);
    cudaGetSymbolAddress((void**)&gu,  g_gu);
    cudaGetSymbolAddress((void**)&act, g_act);
    cudaGetSymbolAddress((void**)&hf,  g_hf);

    cudaFuncSetAttribute((const void*)gemm_tt<0,1,0>, cudaFuncAttributeMaxDynamicSharedMemorySize, GEMM_SMEM_);
    cudaFuncSetAttribute((const void*)gemm_tt<0,0,0>, cudaFuncAttributeMaxDynamicSharedMemorySize, GEMM_SMEM_);
    cudaFuncSetAttribute((const void*)gemm_tt<0,0,1>, cudaFuncAttributeMaxDynamicSharedMemorySize, GEMM_SMEM_);
    cudaFuncSetAttribute((const void*)gemm_tt<1,1,0>, cudaFuncAttributeMaxDynamicSharedMemorySize, GEMM_SMEM_);

    dim3 tb(32, 8);

    // x = hidden_conv^T  (HID x T -> T x HID)
    transpose_k<0><<<dim3(T_ / 32, HID_ / 32), tb>>>(hc, x, HID_, T_);
    // h = rmsnorm(x) * input_ln_w  (tf32-rounded)
    rmsnorm_k<<<T_, 256>>>(x, iln, h);
    // Q projection
    gemm_tt<0,1,0><<<dim3(16, 16, 1), 128, GEMM_SMEM_>>>(h, HID_, 0, wq, HID_, 0, 1,
        q, H_ * D_, 0, nullptr, 0, nullptr, nullptr, HID_, 1.f, 0);
    // K and V projections merged into one launch (z picks B/C)
    gemm_tt<0,1,0><<<dim3(8, 16, 2), 128, GEMM_SMEM_>>>(h, HID_, 0, wk, HID_, 0, 1,
        k, HKV_ * D_, 0, nullptr, 0, wv, v, HID_, 1.f, 0);
    // per-head rmsnorm + rope (rounded)
    qknorm_rope_k<<<T_ * H_ / 8, 256>>>(q, H_, qnw, cs, sn);
    qknorm_rope_k<<<T_ * HKV_ / 8, 256>>>(k, HKV_, knw, cs, sn);
    // vT for PV gemm (rounded during transpose)
    transpose_k<1><<<dim3((HKV_ * D_) / 32, T_ / 32), tb>>>(v, vT, T_, HKV_ * D_);
    // scores = SCALE * q k^T per head (causal tiles only; operands pre-rounded)
    gemm_tt<0,0,0><<<dim3(16, 16, H_), 128, GEMM_SMEM_>>>(q, H_ * D_, D_,
        k, HKV_ * D_, D_, 2, sc, T_, (long)T_ * T_, nullptr, 0, nullptr, nullptr, D_, SCALE_, 1);
    // causal softmax in-place (rounded; zeros masked tail)
    softmax_causal_k<<<dim3(T_, H_), 256>>>(sc);
    // attn @ V  (K capped causally; output rounded for O-proj consumption)
    gemm_tt<0,0,1><<<dim3(1, 16, H_), 128, GEMM_SMEM_>>>(sc, T_, (long)T_ * T_,
        vT, T_, (long)D_ * T_, 2, ao, H_ * D_, D_, nullptr, 0, nullptr, nullptr, T_, 1.f, 2);
    // hidden = x + ao @ wo^T
    gemm_tt<1,1,0><<<dim3(16, 16, 1), 128, GEMM_SMEM_>>>(ao, H_ * D_, 0, wo, H_ * D_, 0, 1,
        hid, HID_, 0, x, HID_, nullptr, nullptr, H_ * D_, 1.f, 0);
    // h2 = rmsnorm(hidden) * post_ln_w  (rounded)
    rmsnorm_k<<<T_, 256>>>(hid, pln, h2);
    // gu = h2 @ w_gate_up^T
    gemm_tt<0,1,0><<<dim3(128, 16, 1), 128, GEMM_SMEM_>>>(h2, HID_, 0, wgu, HID_, 0, 1,
        gu, 2 * I_, 0, nullptr, 0, nullptr, nullptr, HID_, 1.f, 0);
    // act = silu(gate) * up  (rounded)
    swiglu_k<<<(T_ * I_ / 4) / 256, 256>>>(gu, act);
    // hf = hidden + act @ w_down^T
    gemm_tt<1,1,0><<<dim3(16, 16, 1), 128, GEMM_SMEM_>>>(act, I_, 0, wdn, I_, 0, 1,
        hf, HID_, 0, hid, HID_, nullptr, nullptr, I_, 1.f, 0);
    // out = hf^T  (T x HID -> HID x T)
    transpose_k<0><<<dim3(HID_ / 32, T_ / 32), tb>>>(hf, out, T_, HID_);
}